// round 1
// baseline (speedup 1.0000x reference)
#include <cuda_runtime.h>
#include <math.h>

#define N_ATOMS 50000
#define N_EDGES 100000
#define B_G 50
#define M_M 50
#define NPG 1000
#define DIN 32
#define H1D 32
#define H2D 64
#define DE 16
#define AAF 95
#define G_DIM 128
#define K_S 3
#define T_L 6
#define EA 98
#define F1D 64
#define F2D 32
#define F3D 16
#define X0DIM 159   /* H2 + AAF */

// ---------------- scratch (device globals; no allocation allowed) ----------------
__device__ float g_h1[N_ATOMS * H1D];          // conv1 output (pre-relu)
__device__ float g_h2[N_ATOMS * H2D];          // conv2 output (pre-relu)
__device__ float g_aa[B_G * M_M * H2D];        // amino-acid embeddings
__device__ float g_gg[B_G * M_M * G_DIM];      // ARMA mean output
__device__ int   g_aoff[M_M + 1];              // amino CSR offsets
__device__ int   g_asrc[EA];                   // amino CSR src
__device__ float g_anorm[EA];                  // amino CSR norm

// ---------------- amino graph prep: degree, norm, counting-sort to CSR ----------------
__global__ void k_amino_prep(const int* __restrict__ aei) {
    if (threadIdx.x != 0 || blockIdx.x != 0) return;
    int deg[M_M];
    float dinv[M_M];
    int off[M_M + 1];
    int cnt[M_M];
    for (int m = 0; m < M_M; ++m) { deg[m] = 0; cnt[m] = 0; }
    for (int e = 0; e < EA; ++e) deg[aei[EA + e]]++;
    for (int m = 0; m < M_M; ++m)
        dinv[m] = (deg[m] > 0) ? (1.0f / sqrtf((float)deg[m])) : 0.0f;
    off[0] = 0;
    for (int m = 0; m < M_M; ++m) off[m + 1] = off[m] + deg[m];
    for (int e = 0; e < EA; ++e) {
        int s = aei[e], d = aei[EA + e];
        int slot = off[d] + cnt[d]++;
        g_asrc[slot] = s;
        g_anorm[slot] = dinv[s] * dinv[d];
    }
    for (int m = 0; m <= M_M; ++m) g_aoff[m] = off[m];
}

// ---------------- root term conv1: g_h1 = x @ root1 + bias1 ----------------
__global__ void __launch_bounds__(256) k_root1(const float* __restrict__ x,
                                               const float* __restrict__ root1,
                                               const float* __restrict__ bias1) {
    __shared__ float r[DIN * H1D];
    __shared__ float bs[H1D];
    int tid = threadIdx.x;
    for (int i = tid; i < DIN * H1D; i += 256) r[i] = root1[i];
    if (tid < H1D) bs[tid] = bias1[tid];
    __syncthreads();
    int lane = tid & 31;
    int node = blockIdx.x * 8 + (tid >> 5);
    if (node >= N_ATOMS) return;
    float xv = x[node * DIN + lane];
    float acc = bs[lane];
#pragma unroll
    for (int f = 0; f < DIN; ++f)
        acc = fmaf(__shfl_sync(0xffffffffu, xv, f), r[f * H1D + lane], acc);
    g_h1[node * H1D + lane] = acc;
}

// ---------------- root term conv2: g_h2 = relu(h1) @ root2 + bias2 ----------------
__global__ void __launch_bounds__(256) k_root2(const float* __restrict__ root2,
                                               const float* __restrict__ bias2) {
    __shared__ float r[H1D * H2D];
    __shared__ float bs[H2D];
    int tid = threadIdx.x;
    for (int i = tid; i < H1D * H2D; i += 256) r[i] = root2[i];
    if (tid < H2D) bs[tid] = bias2[tid];
    __syncthreads();
    int lane = tid & 31;
    int node = blockIdx.x * 8 + (tid >> 5);
    if (node >= N_ATOMS) return;
    float hv = fmaxf(g_h1[node * H1D + lane], 0.0f);
    float a0 = bs[lane];
    float a1 = bs[32 + lane];
#pragma unroll
    for (int f = 0; f < H1D; ++f) {
        float xf = __shfl_sync(0xffffffffu, hv, f);
        a0 = fmaf(xf, r[f * H2D + lane], a0);
        a1 = fmaf(xf, r[f * H2D + 32 + lane], a1);
    }
    g_h2[node * H2D + lane] = a0;
    g_h2[node * H2D + 32 + lane] = a1;
}

// ---------------- conv1 edge messages (fused bilinear, atomic scatter) ----------------
// sW layout: [17][32][32] — d=0..15 from W_e1, d=16 = edge-MLP bias.
__global__ void __launch_bounds__(256, 2) k_edge1(const float* __restrict__ ea_g,
                                                  const int* __restrict__ eidx,
                                                  const float* __restrict__ We,
                                                  const float* __restrict__ be,
                                                  const float* __restrict__ x) {
    extern __shared__ float sW[];  // 17*1024 floats
    int tid = threadIdx.x;
    for (int i = tid; i < 16 * 1024; i += 256) sW[i] = We[i];
    for (int i = tid; i < 1024; i += 256) sW[16 * 1024 + i] = be[i];
    __syncthreads();
    int e = blockIdx.x * 256 + tid;
    if (e >= N_EDGES) return;
    int src = eidx[e], dst = eidx[N_EDGES + e];

    float ea[17];
    {
        const float4* eap = (const float4*)(ea_g + e * DE);
#pragma unroll
        for (int j = 0; j < 4; ++j) {
            float4 v = eap[j];
            ea[j * 4 + 0] = v.x; ea[j * 4 + 1] = v.y;
            ea[j * 4 + 2] = v.z; ea[j * 4 + 3] = v.w;
        }
        ea[16] = 1.0f;
    }
    float hv[DIN];
    {
        const float4* xp = (const float4*)(x + src * DIN);
#pragma unroll
        for (int j = 0; j < 8; ++j) {
            float4 v = xp[j];
            hv[j * 4 + 0] = v.x; hv[j * 4 + 1] = v.y;
            hv[j * 4 + 2] = v.z; hv[j * 4 + 3] = v.w;
        }
    }
    float acc[32];
#pragma unroll
    for (int o = 0; o < 32; ++o) acc[o] = 0.0f;

#pragma unroll 1
    for (int d = 0; d < 17; ++d) {
        const float ead = ea[d];
        const float4* wd = (const float4*)(sW + d * 1024);
#pragma unroll
        for (int f = 0; f < 32; ++f) {
            const float p = ead * hv[f];
#pragma unroll
            for (int o4 = 0; o4 < 8; ++o4) {
                float4 w = wd[f * 8 + o4];
                acc[o4 * 4 + 0] = fmaf(p, w.x, acc[o4 * 4 + 0]);
                acc[o4 * 4 + 1] = fmaf(p, w.y, acc[o4 * 4 + 1]);
                acc[o4 * 4 + 2] = fmaf(p, w.z, acc[o4 * 4 + 2]);
                acc[o4 * 4 + 3] = fmaf(p, w.w, acc[o4 * 4 + 3]);
            }
        }
    }
    float* ag = g_h1 + dst * H1D;
#pragma unroll
    for (int o = 0; o < 32; ++o) atomicAdd(ag + o, acc[o]);
}

// ---------------- conv2 edge messages (half of fout per launch) ----------------
__global__ void __launch_bounds__(256, 2) k_edge2(const float* __restrict__ ea_g,
                                                  const int* __restrict__ eidx,
                                                  const float* __restrict__ We2,
                                                  const float* __restrict__ be2,
                                                  int o_base) {
    extern __shared__ float sW[];  // 17*1024 floats: slice [17][32][32] of [17][32][64]
    int tid = threadIdx.x;
    for (int i = tid; i < 17 * 1024; i += 256) {
        int d = i >> 10, r = i & 1023, f = r >> 5, o = r & 31;
        sW[i] = (d < 16) ? We2[d * 2048 + f * 64 + o_base + o]
                         : be2[f * 64 + o_base + o];
    }
    __syncthreads();
    int e = blockIdx.x * 256 + tid;
    if (e >= N_EDGES) return;
    int src = eidx[e], dst = eidx[N_EDGES + e];

    float ea[17];
    {
        const float4* eap = (const float4*)(ea_g + e * DE);
#pragma unroll
        for (int j = 0; j < 4; ++j) {
            float4 v = eap[j];
            ea[j * 4 + 0] = v.x; ea[j * 4 + 1] = v.y;
            ea[j * 4 + 2] = v.z; ea[j * 4 + 3] = v.w;
        }
        ea[16] = 1.0f;
    }
    float hv[H1D];
    {
        const float4* hp = (const float4*)(g_h1 + src * H1D);
#pragma unroll
        for (int j = 0; j < 8; ++j) {
            float4 v = hp[j];
            hv[j * 4 + 0] = fmaxf(v.x, 0.0f); hv[j * 4 + 1] = fmaxf(v.y, 0.0f);
            hv[j * 4 + 2] = fmaxf(v.z, 0.0f); hv[j * 4 + 3] = fmaxf(v.w, 0.0f);
        }
    }
    float acc[32];
#pragma unroll
    for (int o = 0; o < 32; ++o) acc[o] = 0.0f;

#pragma unroll 1
    for (int d = 0; d < 17; ++d) {
        const float ead = ea[d];
        const float4* wd = (const float4*)(sW + d * 1024);
#pragma unroll
        for (int f = 0; f < 32; ++f) {
            const float p = ead * hv[f];
#pragma unroll
            for (int o4 = 0; o4 < 8; ++o4) {
                float4 w = wd[f * 8 + o4];
                acc[o4 * 4 + 0] = fmaf(p, w.x, acc[o4 * 4 + 0]);
                acc[o4 * 4 + 1] = fmaf(p, w.y, acc[o4 * 4 + 1]);
                acc[o4 * 4 + 2] = fmaf(p, w.z, acc[o4 * 4 + 2]);
                acc[o4 * 4 + 3] = fmaf(p, w.w, acc[o4 * 4 + 3]);
            }
        }
    }
    float* ag = g_h2 + dst * H2D + o_base;
#pragma unroll
    for (int o = 0; o < 32; ++o) atomicAdd(ag + o, acc[o]);
}

// ---------------- atom attention readout -> g_aa; also zeroes g_gg ----------------
// dynamic smem: sc[1000] | wa[64] | red[128] | wacc[4*50*64]
__global__ void __launch_bounds__(128) k_attn(const int* __restrict__ labels,
                                              const float* __restrict__ wa_g,
                                              const float* __restrict__ ba_g) {
    extern __shared__ float sm[];
    float* sc = sm;
    float* wa = sm + 1000;
    float* red = sm + 1064;
    float* wacc = sm + 1192;  // 12800 floats

    int b = blockIdx.x, tid = threadIdx.x;
    const float* h2b = g_h2 + (size_t)b * NPG * H2D;
    if (tid < 64) wa[tid] = wa_g[tid];
    for (int i = tid; i < 4 * M_M * H2D; i += 128) wacc[i] = 0.0f;
    for (int i = tid; i < M_M * G_DIM; i += 128) g_gg[b * M_M * G_DIM + i] = 0.0f;
    __syncthreads();

    float ba = ba_g[0];
    for (int i = tid; i < NPG; i += 128) {
        const float4* r4 = (const float4*)(h2b + i * H2D);
        float s = ba;
#pragma unroll
        for (int o4 = 0; o4 < 16; ++o4) {
            float4 v = r4[o4];
            s = fmaf(fmaxf(v.x, 0.0f), wa[o4 * 4 + 0], s);
            s = fmaf(fmaxf(v.y, 0.0f), wa[o4 * 4 + 1], s);
            s = fmaf(fmaxf(v.z, 0.0f), wa[o4 * 4 + 2], s);
            s = fmaf(fmaxf(v.w, 0.0f), wa[o4 * 4 + 3], s);
        }
        sc[i] = s;
    }
    __syncthreads();
    // max reduce
    float mx = -1e30f;
    for (int i = tid; i < NPG; i += 128) mx = fmaxf(mx, sc[i]);
    red[tid] = mx;
    __syncthreads();
    for (int s = 64; s > 0; s >>= 1) {
        if (tid < s) red[tid] = fmaxf(red[tid], red[tid + s]);
        __syncthreads();
    }
    mx = red[0];
    __syncthreads();
    // exp + sum
    float se = 0.0f;
    for (int i = tid; i < NPG; i += 128) {
        float e2 = expf(sc[i] - mx);
        sc[i] = e2;
        se += e2;
    }
    red[tid] = se;
    __syncthreads();
    for (int s = 64; s > 0; s >>= 1) {
        if (tid < s) red[tid] += red[tid + s];
        __syncthreads();
    }
    float inv = 1.0f / red[0];
    __syncthreads();

    // per-warp private accumulation (no atomics, no bank conflicts)
    int w = tid >> 5, lane = tid & 31;
    float* wp = wacc + w * (M_M * H2D);
    for (int i = w; i < NPG; i += 4) {
        int m = labels[b * NPG + i];
        float c = sc[i] * inv;
        const float* row = h2b + i * H2D;
        wp[m * H2D + lane]      += c * fmaxf(row[lane], 0.0f);
        wp[m * H2D + 32 + lane] += c * fmaxf(row[32 + lane], 0.0f);
    }
    __syncthreads();
    for (int i = tid; i < M_M * H2D; i += 128) {
        g_aa[b * M_M * H2D + i] =
            wacc[i] + wacc[3200 + i] + wacc[6400 + i] + wacc[9600 + i];
    }
}

// ---------------- ARMA ----------------
__device__ __forceinline__ void arma_mm(float acc[5][4], const float* __restrict__ xs,
                                        int xstride, int Fdim,
                                        const float* __restrict__ w, int m0, int o0) {
    const float* x0p = xs + m0 * xstride;
    const float* x1p = x0p + xstride;
    const float* x2p = x1p + xstride;
    const float* x3p = x2p + xstride;
    const float* x4p = x3p + xstride;
    const float* wp = w + o0;
#pragma unroll 2
    for (int f = 0; f < Fdim; ++f) {
        float4 wv = __ldg((const float4*)(wp + (size_t)f * G_DIM));
        float xf;
        xf = x0p[f];
        acc[0][0] = fmaf(xf, wv.x, acc[0][0]); acc[0][1] = fmaf(xf, wv.y, acc[0][1]);
        acc[0][2] = fmaf(xf, wv.z, acc[0][2]); acc[0][3] = fmaf(xf, wv.w, acc[0][3]);
        xf = x1p[f];
        acc[1][0] = fmaf(xf, wv.x, acc[1][0]); acc[1][1] = fmaf(xf, wv.y, acc[1][1]);
        acc[1][2] = fmaf(xf, wv.z, acc[1][2]); acc[1][3] = fmaf(xf, wv.w, acc[1][3]);
        xf = x2p[f];
        acc[2][0] = fmaf(xf, wv.x, acc[2][0]); acc[2][1] = fmaf(xf, wv.y, acc[2][1]);
        acc[2][2] = fmaf(xf, wv.z, acc[2][2]); acc[2][3] = fmaf(xf, wv.w, acc[2][3]);
        xf = x3p[f];
        acc[3][0] = fmaf(xf, wv.x, acc[3][0]); acc[3][1] = fmaf(xf, wv.y, acc[3][1]);
        acc[3][2] = fmaf(xf, wv.z, acc[3][2]); acc[3][3] = fmaf(xf, wv.w, acc[3][3]);
        xf = x4p[f];
        acc[4][0] = fmaf(xf, wv.x, acc[4][0]); acc[4][1] = fmaf(xf, wv.y, acc[4][1]);
        acc[4][2] = fmaf(xf, wv.z, acc[4][2]); acc[4][3] = fmaf(xf, wv.w, acc[4][3]);
    }
}

// dynamic smem: x0s[50*160] | bufA[50*128] | bufB[50*128]
__global__ void __launch_bounds__(320) k_arma(const float* __restrict__ aaf,
                                              const float* __restrict__ w_init,
                                              const float* __restrict__ w_mid,
                                              const float* __restrict__ w_root,
                                              const float* __restrict__ w_bias) {
    extern __shared__ float sm[];
    float* x0s = sm;            // stride 160
    float* bufA = sm + 8000;    // stride 128
    float* bufB = sm + 14400;   // stride 128

    int b = blockIdx.x / K_S, k = blockIdx.x % K_S;
    int tid = threadIdx.x;
    for (int i = tid; i < M_M * X0DIM; i += 320) {
        int m = i / X0DIM, f = i % X0DIM;
        float v = (f < H2D) ? g_aa[(b * M_M + m) * H2D + f]
                            : aaf[(b * M_M + m) * AAF + (f - H2D)];
        x0s[m * 160 + f] = v;
    }
    __syncthreads();

    int warp = tid >> 5, lane = tid & 31;
    int m0 = warp * 5, o0 = lane * 4;
    float acc[5][4];

    // init: out = x0 @ init_w[k]
#pragma unroll
    for (int mi = 0; mi < 5; ++mi)
#pragma unroll
        for (int j = 0; j < 4; ++j) acc[mi][j] = 0.0f;
    arma_mm(acc, x0s, 160, X0DIM, w_init + (size_t)k * X0DIM * G_DIM, m0, o0);
#pragma unroll
    for (int mi = 0; mi < 5; ++mi)
        *(float4*)(bufA + (m0 + mi) * G_DIM + o0) =
            make_float4(acc[mi][0], acc[mi][1], acc[mi][2], acc[mi][3]);
    __syncthreads();

    for (int t = 0; t < T_L; ++t) {
        const float* cur = bufA;
        if (t > 0) {
#pragma unroll
            for (int mi = 0; mi < 5; ++mi)
#pragma unroll
                for (int j = 0; j < 4; ++j) acc[mi][j] = 0.0f;
            arma_mm(acc, bufA, G_DIM, G_DIM,
                    w_mid + (size_t)((t - 1) * K_S + k) * G_DIM * G_DIM, m0, o0);
#pragma unroll
            for (int mi = 0; mi < 5; ++mi)
                *(float4*)(bufB + (m0 + mi) * G_DIM + o0) =
                    make_float4(acc[mi][0], acc[mi][1], acc[mi][2], acc[mi][3]);
            __syncthreads();
            cur = bufB;
        }
        // root conv
#pragma unroll
        for (int mi = 0; mi < 5; ++mi)
#pragma unroll
            for (int j = 0; j < 4; ++j) acc[mi][j] = 0.0f;
        arma_mm(acc, x0s, 160, X0DIM,
                w_root + (size_t)(t * K_S + k) * X0DIM * G_DIM, m0, o0);
        // propagation over amino CSR
#pragma unroll
        for (int mi = 0; mi < 5; ++mi) {
            int m = m0 + mi;
            int e0 = g_aoff[m], e1 = g_aoff[m + 1];
            for (int e = e0; e < e1; ++e) {
                int s = g_asrc[e];
                float nr = g_anorm[e];
                float4 cv = *(const float4*)(cur + s * G_DIM + o0);
                acc[mi][0] = fmaf(nr, cv.x, acc[mi][0]);
                acc[mi][1] = fmaf(nr, cv.y, acc[mi][1]);
                acc[mi][2] = fmaf(nr, cv.z, acc[mi][2]);
                acc[mi][3] = fmaf(nr, cv.w, acc[mi][3]);
            }
        }
        // bias + relu
        float4 bv = __ldg((const float4*)(w_bias + (t * K_S + k) * G_DIM + o0));
#pragma unroll
        for (int mi = 0; mi < 5; ++mi) {
            acc[mi][0] = fmaxf(acc[mi][0] + bv.x, 0.0f);
            acc[mi][1] = fmaxf(acc[mi][1] + bv.y, 0.0f);
            acc[mi][2] = fmaxf(acc[mi][2] + bv.z, 0.0f);
            acc[mi][3] = fmaxf(acc[mi][3] + bv.w, 0.0f);
        }
        __syncthreads();  // all prop reads of cur done before overwriting bufA
#pragma unroll
        for (int mi = 0; mi < 5; ++mi)
            *(float4*)(bufA + (m0 + mi) * G_DIM + o0) =
                make_float4(acc[mi][0], acc[mi][1], acc[mi][2], acc[mi][3]);
        __syncthreads();
    }
    // mean over K stacks via global reduction
    const float invK = 1.0f / (float)K_S;
#pragma unroll
    for (int mi = 0; mi < 5; ++mi)
#pragma unroll
        for (int j = 0; j < 4; ++j)
            atomicAdd(&g_gg[b * M_M * G_DIM + (m0 + mi) * G_DIM + o0 + j],
                      acc[mi][j] * invK);
}

// ---------------- amino attention + MLP head ----------------
__global__ void __launch_bounds__(128) k_final(const float* __restrict__ waa,
                                               const float* __restrict__ baa,
                                               const float* __restrict__ W1,
                                               const float* __restrict__ b1,
                                               const float* __restrict__ W2,
                                               const float* __restrict__ b2,
                                               const float* __restrict__ W3,
                                               const float* __restrict__ b3,
                                               const float* __restrict__ W4,
                                               const float* __restrict__ b4,
                                               float* __restrict__ out) {
    __shared__ float gs[M_M * G_DIM];
    __shared__ float sc[M_M];
    __shared__ float p[G_DIM];
    __shared__ float f1[F1D];
    __shared__ float f2[F2D];
    __shared__ float f3[F3D];
    int b = blockIdx.x, tid = threadIdx.x;
    for (int i = tid; i < M_M * G_DIM; i += 128) gs[i] = g_gg[b * M_M * G_DIM + i];
    __syncthreads();
    if (tid < M_M) {
        float s = baa[0];
#pragma unroll 4
        for (int o = 0; o < G_DIM; ++o) s = fmaf(gs[tid * G_DIM + o], waa[o], s);
        sc[tid] = s;
    }
    __syncthreads();
    if (tid == 0) {
        float mx = -1e30f;
        for (int m = 0; m < M_M; ++m) mx = fmaxf(mx, sc[m]);
        float se = 0.0f;
        for (int m = 0; m < M_M; ++m) {
            float e = expf(sc[m] - mx);
            sc[m] = e;
            se += e;
        }
        float inv = 1.0f / se;
        for (int m = 0; m < M_M; ++m) sc[m] *= inv;
    }
    __syncthreads();
    {
        float pv = 0.0f;
        for (int m = 0; m < M_M; ++m) pv = fmaf(sc[m], gs[m * G_DIM + tid], pv);
        p[tid] = pv;
    }
    __syncthreads();
    if (tid < F1D) {
        float v = b1[tid];
        for (int i = 0; i < G_DIM; ++i) v = fmaf(p[i], W1[i * F1D + tid], v);
        f1[tid] = fmaxf(v, 0.0f);
    }
    __syncthreads();
    if (tid < F2D) {
        float v = b2[tid];
        for (int i = 0; i < F1D; ++i) v = fmaf(f1[i], W2[i * F2D + tid], v);
        f2[tid] = fmaxf(v, 0.0f);
    }
    __syncthreads();
    if (tid < F3D) {
        float v = b3[tid];
        for (int i = 0; i < F2D; ++i) v = fmaf(f2[i], W3[i * F3D + tid], v);
        f3[tid] = fmaxf(v, 0.0f);
    }
    __syncthreads();
    if (tid == 0) {
        float v = b4[0];
        for (int i = 0; i < F3D; ++i) v = fmaf(f3[i], W4[i], v);
        out[b] = v;
    }
}

// ---------------- launch ----------------
extern "C" void kernel_launch(void* const* d_in, const int* in_sizes, int n_in,
                              void* d_out, int out_size) {
    const float* x              = (const float*)d_in[0];
    const float* edge_attr      = (const float*)d_in[1];
    const float* aa_features    = (const float*)d_in[2];
    const int*   edge_index     = (const int*)d_in[3];
    const int*   monomer_labels = (const int*)d_in[4];
    const int*   amino_edge_idx = (const int*)d_in[5];
    const float* W_e1   = (const float*)d_in[6];
    const float* b_e1   = (const float*)d_in[7];
    const float* root1  = (const float*)d_in[8];
    const float* bias1  = (const float*)d_in[9];
    const float* W_e2   = (const float*)d_in[10];
    const float* b_e2   = (const float*)d_in[11];
    const float* root2  = (const float*)d_in[12];
    const float* bias2  = (const float*)d_in[13];
    const float* Wa_atom = (const float*)d_in[14];
    const float* ba_atom = (const float*)d_in[15];
    const float* arma_init_w = (const float*)d_in[16];
    const float* arma_w      = (const float*)d_in[17];
    const float* arma_root_w = (const float*)d_in[18];
    const float* arma_bias   = (const float*)d_in[19];
    const float* Wa_aa = (const float*)d_in[20];
    const float* ba_aa = (const float*)d_in[21];
    const float* W1 = (const float*)d_in[22];
    const float* b1 = (const float*)d_in[23];
    const float* W2 = (const float*)d_in[24];
    const float* b2 = (const float*)d_in[25];
    const float* W3 = (const float*)d_in[26];
    const float* b3 = (const float*)d_in[27];
    const float* W4 = (const float*)d_in[28];
    const float* b4 = (const float*)d_in[29];
    float* out = (float*)d_out;

    const int EDGE_SMEM = 17 * 1024 * 4;                     // 69632 B
    const int ATTN_SMEM = (1000 + 64 + 128 + 12800) * 4;     // 55968 B
    const int ARMA_SMEM = (8000 + 6400 + 6400) * 4;          // 83200 B
    cudaFuncSetAttribute(k_edge1, cudaFuncAttributeMaxDynamicSharedMemorySize, EDGE_SMEM);
    cudaFuncSetAttribute(k_edge2, cudaFuncAttributeMaxDynamicSharedMemorySize, EDGE_SMEM);
    cudaFuncSetAttribute(k_attn, cudaFuncAttributeMaxDynamicSharedMemorySize, ATTN_SMEM);
    cudaFuncSetAttribute(k_arma, cudaFuncAttributeMaxDynamicSharedMemorySize, ARMA_SMEM);

    k_amino_prep<<<1, 32>>>(amino_edge_idx);
    k_root1<<<(N_ATOMS + 7) / 8, 256>>>(x, root1, bias1);
    k_edge1<<<(N_EDGES + 255) / 256, 256, EDGE_SMEM>>>(edge_attr, edge_index, W_e1, b_e1, x);
    k_root2<<<(N_ATOMS + 7) / 8, 256>>>(root2, bias2);
    k_edge2<<<(N_EDGES + 255) / 256, 256, EDGE_SMEM>>>(edge_attr, edge_index, W_e2, b_e2, 0);
    k_edge2<<<(N_EDGES + 255) / 256, 256, EDGE_SMEM>>>(edge_attr, edge_index, W_e2, b_e2, 32);
    k_attn<<<B_G, 128, ATTN_SMEM>>>(monomer_labels, Wa_atom, ba_atom);
    k_arma<<<B_G * K_S, 320, ARMA_SMEM>>>(aa_features, arma_init_w, arma_w, arma_root_w, arma_bias);
    k_final<<<B_G, 128>>>(Wa_aa, ba_aa, W1, b1, W2, b2, W3, b3, W4, b4, out);
}

// round 2
// speedup vs baseline: 1.1122x; 1.1122x over previous
#include <cuda_runtime.h>
#include <math.h>

#define N_ATOMS 50000
#define N_EDGES 100000
#define B_G 50
#define M_M 50
#define NPG 1000
#define DIN 32
#define H1D 32
#define H2D 64
#define DE 16
#define AAF 95
#define G_DIM 128
#define K_S 3
#define T_L 6
#define EA 98
#define F1D 64
#define F2D 32
#define F3D 16
#define X0DIM 159   /* H2 + AAF */

typedef unsigned long long u64;

// ---------------- f32x2 helpers ----------------
__device__ __forceinline__ u64 pk2(float a, float b) {
    u64 r;
    asm("mov.b64 %0, {%1, %2};" : "=l"(r) : "f"(a), "f"(b));
    return r;
}
__device__ __forceinline__ void fma2(u64& d, u64 a, u64 b) {
    asm("fma.rn.f32x2 %0, %1, %2, %3;" : "=l"(d) : "l"(a), "l"(b), "l"(d));
}
__device__ __forceinline__ void add2(u64& d, u64 a) {
    asm("add.rn.f32x2 %0, %1, %2;" : "=l"(d) : "l"(a), "l"(d));
}
__device__ __forceinline__ float2 up2(u64 v) {
    float2 f;
    asm("mov.b64 {%0, %1}, %2;" : "=f"(f.x), "=f"(f.y) : "l"(v));
    return f;
}
__device__ __forceinline__ void red4(float* p, float a, float b, float c, float d) {
    asm volatile("red.global.add.v4.f32 [%0], {%1, %2, %3, %4};"
                 :: "l"(p), "f"(a), "f"(b), "f"(c), "f"(d) : "memory");
}

// ---------------- scratch (device globals; no allocation allowed) ----------------
__device__ float g_h1[N_ATOMS * H1D];
__device__ float g_h2[N_ATOMS * H2D];
__device__ float g_aa[B_G * M_M * H2D];
__device__ float g_gg[B_G * M_M * G_DIM];
__device__ int   g_aoff[M_M + 1];
__device__ int   g_asrc[EA];
__device__ float g_anorm[EA];

// ---------------- amino graph prep ----------------
__global__ void k_amino_prep(const int* __restrict__ aei) {
    if (threadIdx.x != 0 || blockIdx.x != 0) return;
    int deg[M_M]; float dinv[M_M]; int off[M_M + 1]; int cnt[M_M];
    for (int m = 0; m < M_M; ++m) { deg[m] = 0; cnt[m] = 0; }
    for (int e = 0; e < EA; ++e) deg[aei[EA + e]]++;
    for (int m = 0; m < M_M; ++m)
        dinv[m] = (deg[m] > 0) ? (1.0f / sqrtf((float)deg[m])) : 0.0f;
    off[0] = 0;
    for (int m = 0; m < M_M; ++m) off[m + 1] = off[m] + deg[m];
    for (int e = 0; e < EA; ++e) {
        int s = aei[e], d = aei[EA + e];
        int slot = off[d] + cnt[d]++;
        g_asrc[slot] = s;
        g_anorm[slot] = dinv[s] * dinv[d];
    }
    for (int m = 0; m <= M_M; ++m) g_aoff[m] = off[m];
}

// ---------------- root conv1: thread-per-node, f32x2 ----------------
__global__ void __launch_bounds__(256) k_root1(const float* __restrict__ x,
                                               const float* __restrict__ root1,
                                               const float* __restrict__ bias1) {
    __shared__ float r[DIN * H1D];
    __shared__ float bs[H1D];
    int tid = threadIdx.x;
    for (int i = tid; i < DIN * H1D; i += 256) r[i] = root1[i];
    if (tid < H1D) bs[tid] = bias1[tid];
    __syncthreads();
    int node = blockIdx.x * 256 + tid;
    if (node >= N_ATOMS) return;

    float hv[DIN];
    {
        const float4* xp = (const float4*)(x + node * DIN);
#pragma unroll
        for (int j = 0; j < 8; ++j) {
            float4 v = xp[j];
            hv[j * 4 + 0] = v.x; hv[j * 4 + 1] = v.y;
            hv[j * 4 + 2] = v.z; hv[j * 4 + 3] = v.w;
        }
    }
    u64 acc2[16];
#pragma unroll
    for (int i = 0; i < 16; ++i) acc2[i] = pk2(bs[2 * i], bs[2 * i + 1]);
#pragma unroll
    for (int f = 0; f < DIN; ++f) {
        u64 p2 = pk2(hv[f], hv[f]);
        const ulonglong2* wd = (const ulonglong2*)(r + f * H1D);
#pragma unroll
        for (int o8 = 0; o8 < 8; ++o8) {
            ulonglong2 w = wd[o8];
            fma2(acc2[o8 * 2 + 0], p2, w.x);
            fma2(acc2[o8 * 2 + 1], p2, w.y);
        }
    }
    ulonglong2* og = (ulonglong2*)(g_h1 + node * H1D);
#pragma unroll
    for (int i = 0; i < 8; ++i) {
        ulonglong2 v; v.x = acc2[2 * i]; v.y = acc2[2 * i + 1];
        og[i] = v;
    }
}

// ---------------- root conv2: thread-per-node, f32x2 ----------------
__global__ void __launch_bounds__(256) k_root2(const float* __restrict__ root2,
                                               const float* __restrict__ bias2) {
    __shared__ float r[H1D * H2D];
    __shared__ float bs[H2D];
    int tid = threadIdx.x;
    for (int i = tid; i < H1D * H2D; i += 256) r[i] = root2[i];
    if (tid < H2D) bs[tid] = bias2[tid];
    __syncthreads();
    int node = blockIdx.x * 256 + tid;
    if (node >= N_ATOMS) return;

    float hv[H1D];
    {
        const float4* hp = (const float4*)(g_h1 + node * H1D);
#pragma unroll
        for (int j = 0; j < 8; ++j) {
            float4 v = hp[j];
            hv[j * 4 + 0] = fmaxf(v.x, 0.0f); hv[j * 4 + 1] = fmaxf(v.y, 0.0f);
            hv[j * 4 + 2] = fmaxf(v.z, 0.0f); hv[j * 4 + 3] = fmaxf(v.w, 0.0f);
        }
    }
    u64 acc2[32];
#pragma unroll
    for (int i = 0; i < 32; ++i) acc2[i] = pk2(bs[2 * i], bs[2 * i + 1]);
#pragma unroll
    for (int f = 0; f < H1D; ++f) {
        u64 p2 = pk2(hv[f], hv[f]);
        const ulonglong2* wd = (const ulonglong2*)(r + f * H2D);
#pragma unroll
        for (int o8 = 0; o8 < 16; ++o8) {
            ulonglong2 w = wd[o8];
            fma2(acc2[o8 * 2 + 0], p2, w.x);
            fma2(acc2[o8 * 2 + 1], p2, w.y);
        }
    }
    ulonglong2* og = (ulonglong2*)(g_h2 + node * H2D);
#pragma unroll
    for (int i = 0; i < 16; ++i) {
        ulonglong2 v; v.x = acc2[2 * i]; v.y = acc2[2 * i + 1];
        og[i] = v;
    }
}

// ---------------- conv1 edge messages (fused bilinear, f32x2, red.v4 scatter) ----------------
__global__ void __launch_bounds__(256, 2) k_edge1(const float* __restrict__ ea_g,
                                                  const int* __restrict__ eidx,
                                                  const float* __restrict__ We,
                                                  const float* __restrict__ be,
                                                  const float* __restrict__ x) {
    extern __shared__ float sW[];  // [17][32][32]
    int tid = threadIdx.x;
    for (int i = tid; i < 16 * 1024; i += 256) sW[i] = We[i];
    for (int i = tid; i < 1024; i += 256) sW[16 * 1024 + i] = be[i];
    __syncthreads();
    int e = blockIdx.x * 256 + tid;
    if (e >= N_EDGES) return;
    int src = eidx[e], dst = eidx[N_EDGES + e];

    float ea[17];
    {
        const float4* eap = (const float4*)(ea_g + e * DE);
#pragma unroll
        for (int j = 0; j < 4; ++j) {
            float4 v = eap[j];
            ea[j * 4 + 0] = v.x; ea[j * 4 + 1] = v.y;
            ea[j * 4 + 2] = v.z; ea[j * 4 + 3] = v.w;
        }
        ea[16] = 1.0f;
    }
    float hv[DIN];
    {
        const float4* xp = (const float4*)(x + src * DIN);
#pragma unroll
        for (int j = 0; j < 8; ++j) {
            float4 v = xp[j];
            hv[j * 4 + 0] = v.x; hv[j * 4 + 1] = v.y;
            hv[j * 4 + 2] = v.z; hv[j * 4 + 3] = v.w;
        }
    }
    u64 acc2[16];
#pragma unroll
    for (int i = 0; i < 16; ++i) acc2[i] = 0ull;

#pragma unroll 1
    for (int d = 0; d < 17; ++d) {
        const float ead = ea[d];
        const ulonglong2* wd = (const ulonglong2*)(sW + d * 1024);
#pragma unroll
        for (int f = 0; f < 32; ++f) {
            float p = ead * hv[f];
            u64 p2 = pk2(p, p);
#pragma unroll
            for (int o8 = 0; o8 < 8; ++o8) {
                ulonglong2 w = wd[f * 8 + o8];
                fma2(acc2[o8 * 2 + 0], p2, w.x);
                fma2(acc2[o8 * 2 + 1], p2, w.y);
            }
        }
    }
    float* ag = g_h1 + dst * H1D;
#pragma unroll
    for (int q = 0; q < 8; ++q) {
        float2 lo = up2(acc2[2 * q]), hi = up2(acc2[2 * q + 1]);
        red4(ag + q * 4, lo.x, lo.y, hi.x, hi.y);
    }
}

// ---------------- conv2 edge messages (half of fout per launch) ----------------
__global__ void __launch_bounds__(256, 2) k_edge2(const float* __restrict__ ea_g,
                                                  const int* __restrict__ eidx,
                                                  const float* __restrict__ We2,
                                                  const float* __restrict__ be2,
                                                  int o_base) {
    extern __shared__ float sW[];  // slice [17][32][32] of [17][32][64]
    int tid = threadIdx.x;
    for (int i = tid; i < 17 * 1024; i += 256) {
        int d = i >> 10, r = i & 1023, f = r >> 5, o = r & 31;
        sW[i] = (d < 16) ? We2[d * 2048 + f * 64 + o_base + o]
                         : be2[f * 64 + o_base + o];
    }
    __syncthreads();
    int e = blockIdx.x * 256 + tid;
    if (e >= N_EDGES) return;
    int src = eidx[e], dst = eidx[N_EDGES + e];

    float ea[17];
    {
        const float4* eap = (const float4*)(ea_g + e * DE);
#pragma unroll
        for (int j = 0; j < 4; ++j) {
            float4 v = eap[j];
            ea[j * 4 + 0] = v.x; ea[j * 4 + 1] = v.y;
            ea[j * 4 + 2] = v.z; ea[j * 4 + 3] = v.w;
        }
        ea[16] = 1.0f;
    }
    float hv[H1D];
    {
        const float4* hp = (const float4*)(g_h1 + src * H1D);
#pragma unroll
        for (int j = 0; j < 8; ++j) {
            float4 v = hp[j];
            hv[j * 4 + 0] = fmaxf(v.x, 0.0f); hv[j * 4 + 1] = fmaxf(v.y, 0.0f);
            hv[j * 4 + 2] = fmaxf(v.z, 0.0f); hv[j * 4 + 3] = fmaxf(v.w, 0.0f);
        }
    }
    u64 acc2[16];
#pragma unroll
    for (int i = 0; i < 16; ++i) acc2[i] = 0ull;

#pragma unroll 1
    for (int d = 0; d < 17; ++d) {
        const float ead = ea[d];
        const ulonglong2* wd = (const ulonglong2*)(sW + d * 1024);
#pragma unroll
        for (int f = 0; f < 32; ++f) {
            float p = ead * hv[f];
            u64 p2 = pk2(p, p);
#pragma unroll
            for (int o8 = 0; o8 < 8; ++o8) {
                ulonglong2 w = wd[f * 8 + o8];
                fma2(acc2[o8 * 2 + 0], p2, w.x);
                fma2(acc2[o8 * 2 + 1], p2, w.y);
            }
        }
    }
    float* ag = g_h2 + dst * H2D + o_base;
#pragma unroll
    for (int q = 0; q < 8; ++q) {
        float2 lo = up2(acc2[2 * q]), hi = up2(acc2[2 * q + 1]);
        red4(ag + q * 4, lo.x, lo.y, hi.x, hi.y);
    }
}

// ---------------- atom attention readout -> g_aa; also zeroes g_gg ----------------
__global__ void __launch_bounds__(128) k_attn(const int* __restrict__ labels,
                                              const float* __restrict__ wa_g,
                                              const float* __restrict__ ba_g) {
    extern __shared__ float sm[];
    float* sc = sm;
    float* wa = sm + 1000;
    float* red = sm + 1064;
    float* wacc = sm + 1192;

    int b = blockIdx.x, tid = threadIdx.x;
    const float* h2b = g_h2 + (size_t)b * NPG * H2D;
    if (tid < 64) wa[tid] = wa_g[tid];
    for (int i = tid; i < 4 * M_M * H2D; i += 128) wacc[i] = 0.0f;
    for (int i = tid; i < M_M * G_DIM; i += 128) g_gg[b * M_M * G_DIM + i] = 0.0f;
    __syncthreads();

    float ba = ba_g[0];
    for (int i = tid; i < NPG; i += 128) {
        const float4* r4 = (const float4*)(h2b + i * H2D);
        float s = ba;
#pragma unroll
        for (int o4 = 0; o4 < 16; ++o4) {
            float4 v = r4[o4];
            s = fmaf(fmaxf(v.x, 0.0f), wa[o4 * 4 + 0], s);
            s = fmaf(fmaxf(v.y, 0.0f), wa[o4 * 4 + 1], s);
            s = fmaf(fmaxf(v.z, 0.0f), wa[o4 * 4 + 2], s);
            s = fmaf(fmaxf(v.w, 0.0f), wa[o4 * 4 + 3], s);
        }
        sc[i] = s;
    }
    __syncthreads();
    float mx = -1e30f;
    for (int i = tid; i < NPG; i += 128) mx = fmaxf(mx, sc[i]);
    red[tid] = mx;
    __syncthreads();
    for (int s = 64; s > 0; s >>= 1) {
        if (tid < s) red[tid] = fmaxf(red[tid], red[tid + s]);
        __syncthreads();
    }
    mx = red[0];
    __syncthreads();
    float se = 0.0f;
    for (int i = tid; i < NPG; i += 128) {
        float e2 = expf(sc[i] - mx);
        sc[i] = e2;
        se += e2;
    }
    red[tid] = se;
    __syncthreads();
    for (int s = 64; s > 0; s >>= 1) {
        if (tid < s) red[tid] += red[tid + s];
        __syncthreads();
    }
    float inv = 1.0f / red[0];
    __syncthreads();

    int w = tid >> 5, lane = tid & 31;
    float* wp = wacc + w * (M_M * H2D);
    for (int i = w; i < NPG; i += 4) {
        int m = labels[b * NPG + i];
        float c = sc[i] * inv;
        const float* row = h2b + i * H2D;
        wp[m * H2D + lane]      += c * fmaxf(row[lane], 0.0f);
        wp[m * H2D + 32 + lane] += c * fmaxf(row[32 + lane], 0.0f);
    }
    __syncthreads();
    for (int i = tid; i < M_M * H2D; i += 128) {
        g_aa[b * M_M * H2D + i] =
            wacc[i] + wacc[3200 + i] + wacc[6400 + i] + wacc[9600 + i];
    }
}

// ---------------- ARMA (f32x2 matmuls) ----------------
__device__ __forceinline__ void arma_mm2(u64 acc2[5][2], const float* __restrict__ xs,
                                         int xstride, int Fdim,
                                         const float* __restrict__ w, int m0, int o0) {
    const float* x0p = xs + m0 * xstride;
    const float* x1p = x0p + xstride;
    const float* x2p = x1p + xstride;
    const float* x3p = x2p + xstride;
    const float* x4p = x3p + xstride;
    const float* wp = w + o0;
#pragma unroll 2
    for (int f = 0; f < Fdim; ++f) {
        ulonglong2 wv = *(const ulonglong2*)(wp + (size_t)f * G_DIM);
        u64 x0 = pk2(x0p[f], x0p[f]);
        fma2(acc2[0][0], x0, wv.x); fma2(acc2[0][1], x0, wv.y);
        u64 x1 = pk2(x1p[f], x1p[f]);
        fma2(acc2[1][0], x1, wv.x); fma2(acc2[1][1], x1, wv.y);
        u64 x2 = pk2(x2p[f], x2p[f]);
        fma2(acc2[2][0], x2, wv.x); fma2(acc2[2][1], x2, wv.y);
        u64 x3 = pk2(x3p[f], x3p[f]);
        fma2(acc2[3][0], x3, wv.x); fma2(acc2[3][1], x3, wv.y);
        u64 x4 = pk2(x4p[f], x4p[f]);
        fma2(acc2[4][0], x4, wv.x); fma2(acc2[4][1], x4, wv.y);
    }
}

// dynamic smem: x0s[50*160] | bufA[50*128] | bufB[50*128]
__global__ void __launch_bounds__(320) k_arma(const float* __restrict__ aaf,
                                              const float* __restrict__ w_init,
                                              const float* __restrict__ w_mid,
                                              const float* __restrict__ w_root,
                                              const float* __restrict__ w_bias) {
    extern __shared__ float sm[];
    float* x0s = sm;            // stride 160
    float* bufA = sm + 8000;    // stride 128
    float* bufB = sm + 14400;   // stride 128

    int b = blockIdx.x / K_S, k = blockIdx.x % K_S;
    int tid = threadIdx.x;
    for (int i = tid; i < M_M * X0DIM; i += 320) {
        int m = i / X0DIM, f = i % X0DIM;
        float v = (f < H2D) ? g_aa[(b * M_M + m) * H2D + f]
                            : aaf[(b * M_M + m) * AAF + (f - H2D)];
        x0s[m * 160 + f] = v;
    }
    __syncthreads();

    int warp = tid >> 5, lane = tid & 31;
    int m0 = warp * 5, o0 = lane * 4;
    u64 acc2[5][2];

#pragma unroll
    for (int mi = 0; mi < 5; ++mi) { acc2[mi][0] = 0ull; acc2[mi][1] = 0ull; }
    arma_mm2(acc2, x0s, 160, X0DIM, w_init + (size_t)k * X0DIM * G_DIM, m0, o0);
#pragma unroll
    for (int mi = 0; mi < 5; ++mi) {
        ulonglong2 v; v.x = acc2[mi][0]; v.y = acc2[mi][1];
        *(ulonglong2*)(bufA + (m0 + mi) * G_DIM + o0) = v;
    }
    __syncthreads();

    float accf[5][4];
    for (int t = 0; t < T_L; ++t) {
        const float* cur = bufA;
        if (t > 0) {
#pragma unroll
            for (int mi = 0; mi < 5; ++mi) { acc2[mi][0] = 0ull; acc2[mi][1] = 0ull; }
            arma_mm2(acc2, bufA, G_DIM, G_DIM,
                     w_mid + (size_t)((t - 1) * K_S + k) * G_DIM * G_DIM, m0, o0);
#pragma unroll
            for (int mi = 0; mi < 5; ++mi) {
                ulonglong2 v; v.x = acc2[mi][0]; v.y = acc2[mi][1];
                *(ulonglong2*)(bufB + (m0 + mi) * G_DIM + o0) = v;
            }
            __syncthreads();
            cur = bufB;
        }
#pragma unroll
        for (int mi = 0; mi < 5; ++mi) { acc2[mi][0] = 0ull; acc2[mi][1] = 0ull; }
        arma_mm2(acc2, x0s, 160, X0DIM,
                 w_root + (size_t)(t * K_S + k) * X0DIM * G_DIM, m0, o0);
#pragma unroll
        for (int mi = 0; mi < 5; ++mi) {
            int m = m0 + mi;
            int e0 = g_aoff[m], e1 = g_aoff[m + 1];
            for (int e = e0; e < e1; ++e) {
                int s = g_asrc[e];
                u64 nr2 = pk2(g_anorm[e], g_anorm[e]);
                ulonglong2 cv = *(const ulonglong2*)(cur + s * G_DIM + o0);
                fma2(acc2[mi][0], nr2, cv.x);
                fma2(acc2[mi][1], nr2, cv.y);
            }
        }
        // bias + relu
        ulonglong2 bv = *(const ulonglong2*)(w_bias + (t * K_S + k) * G_DIM + o0);
#pragma unroll
        for (int mi = 0; mi < 5; ++mi) {
            add2(acc2[mi][0], bv.x);
            add2(acc2[mi][1], bv.y);
            float2 lo = up2(acc2[mi][0]), hi = up2(acc2[mi][1]);
            accf[mi][0] = fmaxf(lo.x, 0.0f); accf[mi][1] = fmaxf(lo.y, 0.0f);
            accf[mi][2] = fmaxf(hi.x, 0.0f); accf[mi][3] = fmaxf(hi.y, 0.0f);
        }
        __syncthreads();
#pragma unroll
        for (int mi = 0; mi < 5; ++mi)
            *(float4*)(bufA + (m0 + mi) * G_DIM + o0) =
                make_float4(accf[mi][0], accf[mi][1], accf[mi][2], accf[mi][3]);
        __syncthreads();
    }
    const float invK = 1.0f / (float)K_S;
#pragma unroll
    for (int mi = 0; mi < 5; ++mi)
        red4(&g_gg[b * M_M * G_DIM + (m0 + mi) * G_DIM + o0],
             accf[mi][0] * invK, accf[mi][1] * invK,
             accf[mi][2] * invK, accf[mi][3] * invK);
}

// ---------------- amino attention + MLP head ----------------
__global__ void __launch_bounds__(128) k_final(const float* __restrict__ waa,
                                               const float* __restrict__ baa,
                                               const float* __restrict__ W1,
                                               const float* __restrict__ b1,
                                               const float* __restrict__ W2,
                                               const float* __restrict__ b2,
                                               const float* __restrict__ W3,
                                               const float* __restrict__ b3,
                                               const float* __restrict__ W4,
                                               const float* __restrict__ b4,
                                               float* __restrict__ out) {
    __shared__ float gs[M_M * G_DIM];
    __shared__ float sc[M_M];
    __shared__ float p[G_DIM];
    __shared__ float f1[F1D];
    __shared__ float f2[F2D];
    __shared__ float f3[F3D];
    int b = blockIdx.x, tid = threadIdx.x;
    for (int i = tid; i < M_M * G_DIM; i += 128) gs[i] = g_gg[b * M_M * G_DIM + i];
    __syncthreads();
    if (tid < M_M) {
        float s = baa[0];
#pragma unroll 4
        for (int o = 0; o < G_DIM; ++o) s = fmaf(gs[tid * G_DIM + o], waa[o], s);
        sc[tid] = s;
    }
    __syncthreads();
    if (tid == 0) {
        float mx = -1e30f;
        for (int m = 0; m < M_M; ++m) mx = fmaxf(mx, sc[m]);
        float se = 0.0f;
        for (int m = 0; m < M_M; ++m) {
            float e = expf(sc[m] - mx);
            sc[m] = e;
            se += e;
        }
        float inv = 1.0f / se;
        for (int m = 0; m < M_M; ++m) sc[m] *= inv;
    }
    __syncthreads();
    {
        float pv = 0.0f;
        for (int m = 0; m < M_M; ++m) pv = fmaf(sc[m], gs[m * G_DIM + tid], pv);
        p[tid] = pv;
    }
    __syncthreads();
    if (tid < F1D) {
        float v = b1[tid];
        for (int i = 0; i < G_DIM; ++i) v = fmaf(p[i], W1[i * F1D + tid], v);
        f1[tid] = fmaxf(v, 0.0f);
    }
    __syncthreads();
    if (tid < F2D) {
        float v = b2[tid];
        for (int i = 0; i < F1D; ++i) v = fmaf(f1[i], W2[i * F2D + tid], v);
        f2[tid] = fmaxf(v, 0.0f);
    }
    __syncthreads();
    if (tid < F3D) {
        float v = b3[tid];
        for (int i = 0; i < F2D; ++i) v = fmaf(f2[i], W3[i * F3D + tid], v);
        f3[tid] = fmaxf(v, 0.0f);
    }
    __syncthreads();
    if (tid == 0) {
        float v = b4[0];
        for (int i = 0; i < F3D; ++i) v = fmaf(f3[i], W4[i], v);
        out[b] = v;
    }
}

// ---------------- launch ----------------
extern "C" void kernel_launch(void* const* d_in, const int* in_sizes, int n_in,
                              void* d_out, int out_size) {
    const float* x              = (const float*)d_in[0];
    const float* edge_attr      = (const float*)d_in[1];
    const float* aa_features    = (const float*)d_in[2];
    const int*   edge_index     = (const int*)d_in[3];
    const int*   monomer_labels = (const int*)d_in[4];
    const int*   amino_edge_idx = (const int*)d_in[5];
    const float* W_e1   = (const float*)d_in[6];
    const float* b_e1   = (const float*)d_in[7];
    const float* root1  = (const float*)d_in[8];
    const float* bias1  = (const float*)d_in[9];
    const float* W_e2   = (const float*)d_in[10];
    const float* b_e2   = (const float*)d_in[11];
    const float* root2  = (const float*)d_in[12];
    const float* bias2  = (const float*)d_in[13];
    const float* Wa_atom = (const float*)d_in[14];
    const float* ba_atom = (const float*)d_in[15];
    const float* arma_init_w = (const float*)d_in[16];
    const float* arma_w      = (const float*)d_in[17];
    const float* arma_root_w = (const float*)d_in[18];
    const float* arma_bias   = (const float*)d_in[19];
    const float* Wa_aa = (const float*)d_in[20];
    const float* ba_aa = (const float*)d_in[21];
    const float* W1 = (const float*)d_in[22];
    const float* b1 = (const float*)d_in[23];
    const float* W2 = (const float*)d_in[24];
    const float* b2 = (const float*)d_in[25];
    const float* W3 = (const float*)d_in[26];
    const float* b3 = (const float*)d_in[27];
    const float* W4 = (const float*)d_in[28];
    const float* b4 = (const float*)d_in[29];
    float* out = (float*)d_out;

    const int EDGE_SMEM = 17 * 1024 * 4;
    const int ATTN_SMEM = (1000 + 64 + 128 + 12800) * 4;
    const int ARMA_SMEM = (8000 + 6400 + 6400) * 4;
    cudaFuncSetAttribute(k_edge1, cudaFuncAttributeMaxDynamicSharedMemorySize, EDGE_SMEM);
    cudaFuncSetAttribute(k_edge2, cudaFuncAttributeMaxDynamicSharedMemorySize, EDGE_SMEM);
    cudaFuncSetAttribute(k_attn, cudaFuncAttributeMaxDynamicSharedMemorySize, ATTN_SMEM);
    cudaFuncSetAttribute(k_arma, cudaFuncAttributeMaxDynamicSharedMemorySize, ARMA_SMEM);

    k_amino_prep<<<1, 32>>>(amino_edge_idx);
    k_root1<<<(N_ATOMS + 255) / 256, 256>>>(x, root1, bias1);
    k_edge1<<<(N_EDGES + 255) / 256, 256, EDGE_SMEM>>>(edge_attr, edge_index, W_e1, b_e1, x);
    k_root2<<<(N_ATOMS + 255) / 256, 256>>>(root2, bias2);
    k_edge2<<<(N_EDGES + 255) / 256, 256, EDGE_SMEM>>>(edge_attr, edge_index, W_e2, b_e2, 0);
    k_edge2<<<(N_EDGES + 255) / 256, 256, EDGE_SMEM>>>(edge_attr, edge_index, W_e2, b_e2, 32);
    k_attn<<<B_G, 128, ATTN_SMEM>>>(monomer_labels, Wa_atom, ba_atom);
    k_arma<<<B_G * K_S, 320, ARMA_SMEM>>>(aa_features, arma_init_w, arma_w, arma_root_w, arma_bias);
    k_final<<<B_G, 128>>>(Wa_aa, ba_aa, W1, b1, W2, b2, W3, b3, W4, b4, out);
}